// round 6
// baseline (speedup 1.0000x reference)
#include <cuda_runtime.h>
#include <cuda_bf16.h>
#include <math.h>

// Problem constants
#define N_Q   32768
#define M_R   16384
#define KNN   8

// Spatial grid: 32^3 cells of size 3.0 covering [-48, 48]^3 (4.8 sigma).
// Points outside are clamped into edge cells (safe: clamping only moves a
// point's CELL inward, so it is visited no later than its true distance
// warrants, and edge cells make the termination bound infinite on that side).
#define GD        32
#define CELLS     (GD * GD * GD)        // 32768
#define HCELL     3.0f
#define INV_HCELL (1.0f / 3.0f)
#define HWORLD    48.0f

#define SCAN_T 1024
#define CHUNK  (CELLS / SCAN_T)          // 32

// ---- device scratch (allocation-free rule) ----
__device__ int    g_cntR[CELLS], g_startR[CELLS], g_curR[CELLS];
__device__ int    g_cntQ[CELLS], g_startQ[CELLS], g_curQ[CELLS];
__device__ float4 g_refS[M_R];   // sorted refs: (-2x, -2y, -2z, |r|^2)
__device__ int    g_refId[M_R];  // sorted pos -> original ref index
__device__ float4 g_qS[N_Q];     // sorted queries: (x, y, z, |q|^2)
__device__ int    g_qId[N_Q];    // sorted pos -> original query index

__device__ __forceinline__ int clampi(int v, int lo, int hi) {
    return v < lo ? lo : (v > hi ? hi : v);
}

__device__ __forceinline__ void cellCoords(float x, float y, float z,
                                           int& cx, int& cy, int& cz) {
    cx = clampi((int)floorf((x + HWORLD) * INV_HCELL), 0, GD - 1);
    cy = clampi((int)floorf((y + HWORLD) * INV_HCELL), 0, GD - 1);
    cz = clampi((int)floorf((z + HWORLD) * INV_HCELL), 0, GD - 1);
}

__device__ __forceinline__ int flatCell(int cx, int cy, int cz) {
    return (cz * GD + cy) * GD + cx;
}

// ---------------------------------------------------------------------------
__global__ void zero_kernel() {
    int i = blockIdx.x * blockDim.x + threadIdx.x;
    if (i < CELLS)           g_cntR[i] = 0;
    else if (i < 2 * CELLS)  g_cntQ[i - CELLS] = 0;
}

__global__ void count_ref(const float* __restrict__ ref) {
    int i = blockIdx.x * blockDim.x + threadIdx.x;
    if (i >= M_R) return;
    int cx, cy, cz;
    cellCoords(ref[3 * i], ref[3 * i + 1], ref[3 * i + 2], cx, cy, cz);
    atomicAdd(&g_cntR[flatCell(cx, cy, cz)], 1);
}

__global__ void count_qry(const float* __restrict__ q) {
    int i = blockIdx.x * blockDim.x + threadIdx.x;
    if (i >= N_Q) return;
    int cx, cy, cz;
    cellCoords(q[3 * i], q[3 * i + 1], q[3 * i + 2], cx, cy, cz);
    atomicAdd(&g_cntQ[flatCell(cx, cy, cz)], 1);
}

// Exclusive scan over CELLS counts; block 0 handles refs, block 1 queries.
__global__ __launch_bounds__(SCAN_T) void scan_kernel() {
    const int* cnt;
    int *start, *cur;
    if (blockIdx.x == 0) { cnt = g_cntR; start = g_startR; cur = g_curR; }
    else                 { cnt = g_cntQ; start = g_startQ; cur = g_curQ; }

    __shared__ int sh[SCAN_T];
    int t = threadIdx.x;
    int base = t * CHUNK;

    int s = 0;
#pragma unroll
    for (int j = 0; j < CHUNK; ++j) s += cnt[base + j];
    sh[t] = s;
    __syncthreads();

    for (int off = 1; off < SCAN_T; off <<= 1) {
        int v = (t >= off) ? sh[t - off] : 0;
        __syncthreads();
        sh[t] += v;
        __syncthreads();
    }

    int run = sh[t] - s;  // exclusive prefix for this thread's chunk
#pragma unroll
    for (int j = 0; j < CHUNK; ++j) {
        int c = cnt[base + j];
        start[base + j] = run;
        cur[base + j]   = run;
        run += c;
    }
}

__global__ void scatter_ref(const float* __restrict__ ref) {
    int i = blockIdx.x * blockDim.x + threadIdx.x;
    if (i >= M_R) return;
    float x = ref[3 * i], y = ref[3 * i + 1], z = ref[3 * i + 2];
    int cx, cy, cz;
    cellCoords(x, y, z, cx, cy, cz);
    int p = atomicAdd(&g_curR[flatCell(cx, cy, cz)], 1);
    g_refS[p]  = make_float4(-2.0f * x, -2.0f * y, -2.0f * z, x * x + y * y + z * z);
    g_refId[p] = i;
}

__global__ void scatter_qry(const float* __restrict__ q) {
    int i = blockIdx.x * blockDim.x + threadIdx.x;
    if (i >= N_Q) return;
    float x = q[3 * i], y = q[3 * i + 1], z = q[3 * i + 2];
    int cx, cy, cz;
    cellCoords(x, y, z, cx, cy, cz);
    int p = atomicAdd(&g_curQ[flatCell(cx, cy, cz)], 1);
    g_qS[p]  = make_float4(x, y, z, x * x + y * y + z * z);
    g_qId[p] = i;
}

// Sorted-ascending 8-best insertion; caller guarantees d < b[7].
// Strict '<' keeps earlier-seen entries ahead on ties.
__device__ __forceinline__ void insert8(float d, int id, float (&b)[KNN], int (&bi)[KNN]) {
    b[7] = d; bi[7] = id;
#pragma unroll
    for (int k = 7; k > 0; --k) {
        if (b[k] < b[k - 1]) {
            float t = b[k];  b[k] = b[k - 1];  b[k - 1] = t;
            int   u = bi[k]; bi[k] = bi[k - 1]; bi[k - 1] = u;
        }
    }
}

// ---------------------------------------------------------------------------
// KNN over the grid: one thread per SORTED query (warp-coherent cells).
// Expanding Chebyshev shells; exact termination via distance-to-box bound.
// d' = |r|^2 - 2 q.r  (true d^2 = d' + |q|^2, per-query constant).
// ---------------------------------------------------------------------------
__global__ __launch_bounds__(64) void knn_kernel(const float* __restrict__ flow,
                                                 float* __restrict__ out) {
    int t = blockIdx.x * 64 + threadIdx.x;
    float4 qp = g_qS[t];
    const float qx = qp.x, qy = qp.y, qz = qp.z, q2 = qp.w;

    int cx, cy, cz;
    cellCoords(qx, qy, qz, cx, cy, cz);

    float b[KNN];
    int   bi[KNN];
#pragma unroll
    for (int k = 0; k < KNN; ++k) { b[k] = __int_as_float(0x7f800000); bi[k] = 0; }

    for (int s = 0; s < GD; ++s) {
        int x0 = max(cx - s, 0), x1 = min(cx + s, GD - 1);
        int y0 = max(cy - s, 0), y1 = min(cy + s, GD - 1);
        int z0 = max(cz - s, 0), z1 = min(cz + s, GD - 1);

        for (int zz = z0; zz <= z1; ++zz) {
            int dz = abs(zz - cz);
            for (int yy = y0; yy <= y1; ++yy) {
                int dyz = max(abs(yy - cy), dz);
                for (int xx = x0; xx <= x1; ++xx) {
                    if (max(abs(xx - cx), dyz) != s) continue;   // ring only
                    int c   = flatCell(xx, yy, zz);
                    int beg = g_startR[c];
                    int end = beg + g_cntR[c];
                    for (int j = beg; j < end; ++j) {
                        float4 r = g_refS[j];
                        float d = fmaf(r.x, qx, fmaf(r.y, qy, fmaf(r.z, qz, r.w)));
                        if (d < b[7]) insert8(d, j, b, bi);
                    }
                }
            }
        }

        // Full grid covered -> everything examined.
        bool full = (x0 == 0) && (y0 == 0) && (z0 == 0) &&
                    (x1 == GD - 1) && (y1 == GD - 1) && (z1 == GD - 1);
        if (full) break;

        // Termination: any unvisited point lies outside the visited box.
        // Edge-clipped sides extend to infinity (clamped points live there).
        float lox = (x0 == 0)      ? -1e30f : (x0 * HCELL - HWORLD);
        float hix = (x1 == GD - 1) ?  1e30f : ((x1 + 1) * HCELL - HWORLD);
        float loy = (y0 == 0)      ? -1e30f : (y0 * HCELL - HWORLD);
        float hiy = (y1 == GD - 1) ?  1e30f : ((y1 + 1) * HCELL - HWORLD);
        float loz = (z0 == 0)      ? -1e30f : (z0 * HCELL - HWORLD);
        float hiz = (z1 == GD - 1) ?  1e30f : ((z1 + 1) * HCELL - HWORLD);

        float m = fminf(qx - lox, hix - qx);
        m = fminf(m, fminf(qy - loy, hiy - qy));
        m = fminf(m, fminf(qz - loz, hiz - qz));

        if (b[7] < 1e30f && m > 0.0f) {
            float d8sq = fmaxf(b[7] + q2, 0.0f);
            if (m * m >= d8sq) break;
        }
    }

    // IDW weights: POWER=2 -> w = 1/(d^2 + eps); no sqrt needed.
    float wsum = 0.0f, ax = 0.0f, ay = 0.0f, az = 0.0f;
#pragma unroll
    for (int k = 0; k < KNN; ++k) {
        float d2 = fmaxf(b[k] + q2, 0.0f);
        float w  = 1.0f / (d2 + 1e-8f);
        int  id  = g_refId[bi[k]];
        wsum += w;
        ax = fmaf(w, flow[3 * id + 0], ax);
        ay = fmaf(w, flow[3 * id + 1], ay);
        az = fmaf(w, flow[3 * id + 2], az);
    }
    float inv = 1.0f / wsum;

    int qo = g_qId[t];
    out[3 * qo + 0] = ax * inv;
    out[3 * qo + 1] = ay * inv;
    out[3 * qo + 2] = az * inv;
}

// ---------------------------------------------------------------------------
extern "C" void kernel_launch(void* const* d_in, const int* in_sizes, int n_in,
                              void* d_out, int out_size) {
    const float* q   = (const float*)d_in[0];  // query_points [N,3]
    const float* r   = (const float*)d_in[1];  // ref_points   [M,3]
    const float* f   = (const float*)d_in[2];  // ref_flow     [M,3]
    float*       out = (float*)d_out;          // [N,3]

    zero_kernel<<<(2 * CELLS + 255) / 256, 256>>>();
    count_ref<<<(M_R + 255) / 256, 256>>>(r);
    count_qry<<<(N_Q + 255) / 256, 256>>>(q);
    scan_kernel<<<2, SCAN_T>>>();
    scatter_ref<<<(M_R + 255) / 256, 256>>>(r);
    scatter_qry<<<(N_Q + 255) / 256, 256>>>(q);
    knn_kernel<<<N_Q / 64, 64>>>(f, out);
}